// round 9
// baseline (speedup 1.0000x reference)
#include <cuda_runtime.h>
#include <cuda_fp16.h>
#include <cstdint>

// ---------------- problem dims ----------------
#define BS    4
#define SEQ   4096
#define DIN   1024
#define HDIM  1024
#define M_TOTAL (BS*SEQ)       // 16384
#define NCHUNK 64
#define CHUNK  (SEQ/NCHUNK)    // 64
#define NCHAIN (BS*4)          // 16 chains (batch x hgroup)

// ---------------- GEMM tiling ----------------
#define BM 128
#define BN 128
#define BK 64
#define KTILES (DIN/BK)        // 16
#define STAGES 4

#define TILE_BYTES (128*128)
#define STAGE_BYTES (3*TILE_BYTES)         // 48 KB
#define DYN_SMEM (STAGES*STAGE_BYTES)      // 192 KB
#define SCAN_SMEM (CHUNK*256*4)            // 64 KB

// ---------------- scratch ----------------
__device__ uint32_t g_AB[(size_t)M_TOTAL*HDIM]; // packed half2 (a, b)  64 MB
__device__ float g_AggA[BS*NCHUNK*HDIM];
__device__ float g_AggB[BS*NCHUNK*HDIM];
__device__ float g_Inc [BS*NCHUNK*HDIM];
__device__ int   g_Flag[NCHAIN*NCHUNK*256];     // per-channel flags (1 MB)
__device__ int   g_Ticket;
__device__ __half g_x16[(size_t)M_TOTAL*DIN];
__device__ __half g_wz16[HDIM*DIN];
__device__ __half g_wh16[HDIM*DIN];

#define NFLAGS (NCHAIN*NCHUNK*256)   // 262144

// ---------------- helpers ----------------
__device__ __forceinline__ uint32_t smem_u32(const void* p) {
    uint32_t a;
    asm("{ .reg .u64 t; cvta.to.shared.u64 t, %1; cvt.u32.u64 %0, t; }"
        : "=r"(a) : "l"(p));
    return a;
}

__device__ __forceinline__ void cp_async16(uint32_t saddr, const void* gptr) {
    asm volatile("cp.async.cg.shared.global [%0], [%1], 16;"
                 :: "r"(saddr), "l"(gptr) : "memory");
}
#define CP_COMMIT()  asm volatile("cp.async.commit_group;" ::: "memory")
#define CP_WAIT2()   asm volatile("cp.async.wait_group 2;" ::: "memory")
#define CP_WAIT0()   asm volatile("cp.async.wait_group 0;" ::: "memory")

__device__ __forceinline__ void ldmatrix_x4(uint32_t* r, uint32_t addr) {
    asm volatile("ldmatrix.sync.aligned.m8n8.x4.shared.b16 {%0,%1,%2,%3}, [%4];"
                 : "=r"(r[0]), "=r"(r[1]), "=r"(r[2]), "=r"(r[3]) : "r"(addr));
}

__device__ __forceinline__ void mma_fp16(float* d, const uint32_t* a,
                                         uint32_t b0, uint32_t b1) {
    asm volatile(
        "mma.sync.aligned.m16n8k16.row.col.f32.f16.f16.f32 "
        "{%0,%1,%2,%3}, {%4,%5,%6,%7}, {%8,%9}, {%0,%1,%2,%3};"
        : "+f"(d[0]), "+f"(d[1]), "+f"(d[2]), "+f"(d[3])
        : "r"(a[0]), "r"(a[1]), "r"(a[2]), "r"(a[3]), "r"(b0), "r"(b1));
}

__device__ __forceinline__ float g_fn(float x) {
    return (x >= 0.0f) ? (x + 0.5f) : 1.0f / (1.0f + __expf(-x));
}

__device__ __forceinline__ uint32_t pack_ab(float a, float b) {
    __half2 h = __floats2half2_rn(a, b);
    return *(uint32_t*)&h;
}
__device__ __forceinline__ void unpack_ab(uint32_t u, float& a, float& b) {
    __half2 h = *(__half2*)&u;
    a = __low2float(h);
    b = __high2float(h);
}

// ---------------- fp32 -> fp16 convert + scan-state init ----------------
#define CVT_X  (M_TOTAL*DIN/4)
#define CVT_W  (HDIM*DIN/4)
__global__ void convert_kernel(const float* __restrict__ x,
                               const float* __restrict__ Wz,
                               const float* __restrict__ Wh)
{
    const int i = blockIdx.x * blockDim.x + threadIdx.x;
    if (i < NFLAGS) g_Flag[i] = 0;          // reset lookback state each launch
    if (i == NFLAGS) g_Ticket = 0;
    const float* src; __half* dst; int j;
    if (i < CVT_X)                 { src = x;  dst = g_x16;  j = i; }
    else if (i < CVT_X + CVT_W)    { src = Wz; dst = g_wz16; j = i - CVT_X; }
    else                           { src = Wh; dst = g_wh16; j = i - CVT_X - CVT_W; }
    float4 v = *(const float4*)(src + (size_t)j * 4);
    __half2 h0 = __floats2half2_rn(v.x, v.y);
    __half2 h1 = __floats2half2_rn(v.z, v.w);
    uint2 pk = make_uint2(*(uint32_t*)&h0, *(uint32_t*)&h1);
    *(uint2*)(dst + (size_t)j * 4) = pk;
}

// ---------------- fused dual GEMM (fp16 mma) + gate epilogue ----------------
__global__ void __launch_bounds__(256, 1)
gemm_gate_kernel(const float* __restrict__ bz, const float* __restrict__ bh)
{
    extern __shared__ __align__(16) char dyn_smem[];
    __shared__ float sbz[BN], sbh[BN];

    const uint32_t dynb = smem_u32(dyn_smem);
    const int tid  = threadIdx.x;
    const int warp = tid >> 5;
    const int lane = tid & 31;
    const int n0 = blockIdx.x * BN;
    const int m0 = blockIdx.y * BM;

    const int wm = warp >> 2;
    const int wn = warp & 3;

    if (tid < BN) { sbz[tid] = bz[n0 + tid]; sbh[tid] = bh[n0 + tid]; }

    uint32_t stA[STAGES], stBz[STAGES], stBh[STAGES];
#pragma unroll
    for (int s = 0; s < STAGES; s++) {
        stA[s]  = dynb + s * STAGE_BYTES;
        stBz[s] = stA[s] + TILE_BYTES;
        stBh[s] = stBz[s] + TILE_BYTES;
    }

    auto load_stage = [&](int kt, int s) {
        const int kb = kt * BK;
#pragma unroll
        for (int i = 0; i < 4; i++) {
            int v = tid + i * 256, r = v >> 3, c = v & 7;
            uint32_t off = (uint32_t)(r * 128 + ((c ^ (r & 7)) << 4));
            cp_async16(stA[s] + off,  g_x16  + (size_t)(m0 + r) * DIN + kb + c * 8);
            cp_async16(stBz[s] + off, g_wz16 + (size_t)(n0 + r) * DIN + kb + c * 8);
            cp_async16(stBh[s] + off, g_wh16 + (size_t)(n0 + r) * DIN + kb + c * 8);
        }
    };

    float acc[2][4][4][4];
#pragma unroll
    for (int o = 0; o < 2; o++)
#pragma unroll
        for (int a = 0; a < 4; a++)
#pragma unroll
            for (int b = 0; b < 4; b++)
#pragma unroll
                for (int c = 0; c < 4; c++) acc[o][a][b][c] = 0.f;

    load_stage(0, 0); CP_COMMIT();
    load_stage(1, 1); CP_COMMIT();
    load_stage(2, 2); CP_COMMIT();

    const int lrow = lane & 15;
    const int lkh  = lane >> 4;

    uint32_t afrag[2][4][4];
    uint32_t bfZ[2][2][4];
    uint32_t bfH[2][2][4];

    for (int kt = 0; kt < KTILES; kt++) {
        CP_WAIT2();
        __syncthreads();
        if (kt + 3 < KTILES) load_stage(kt + 3, (kt + 3) % STAGES);
        CP_COMMIT();

        const int s = kt % STAGES;
        const uint32_t baseA = stA[s], baseZ = stBz[s], baseH = stBh[s];

        auto frag_load = [&](int ks, int buf) {
            const int ch = ks * 2 + lkh;
#pragma unroll
            for (int mf = 0; mf < 4; mf++) {
                const int row = wm * 64 + mf * 16 + lrow;
                ldmatrix_x4(afrag[buf][mf], baseA + row * 128 + ((ch ^ (row & 7)) << 4));
            }
#pragma unroll
            for (int g = 0; g < 2; g++) {
                const int row = wn * 32 + g * 16 + lrow;
                const uint32_t soff = row * 128 + ((ch ^ (row & 7)) << 4);
                ldmatrix_x4(bfZ[buf][g], baseZ + soff);
                ldmatrix_x4(bfH[buf][g], baseH + soff);
            }
        };

        frag_load(0, 0);
#pragma unroll
        for (int ks = 0; ks < 4; ks++) {
            const int cur = ks & 1;
            if (ks < 3) frag_load(ks + 1, cur ^ 1);
#pragma unroll
            for (int g = 0; g < 2; g++) {
#pragma unroll
                for (int mf = 0; mf < 4; mf++) {
                    mma_fp16(acc[0][mf][g * 2 + 0], afrag[cur][mf], bfZ[cur][g][0], bfZ[cur][g][2]);
                    mma_fp16(acc[0][mf][g * 2 + 1], afrag[cur][mf], bfZ[cur][g][1], bfZ[cur][g][3]);
                    mma_fp16(acc[1][mf][g * 2 + 0], afrag[cur][mf], bfH[cur][g][0], bfH[cur][g][2]);
                    mma_fp16(acc[1][mf][g * 2 + 1], afrag[cur][mf], bfH[cur][g][1], bfH[cur][g][3]);
                }
            }
        }
    }
    __syncthreads();

    // ---------- epilogue: gates + store packed (a,b) ----------
#pragma unroll
    for (int mf = 0; mf < 4; mf++) {
#pragma unroll
        for (int nf = 0; nf < 4; nf++) {
            const int nl = wn * 32 + nf * 8 + (lane & 3) * 2;
            const float bz0 = sbz[nl], bz1 = sbz[nl + 1];
            const float bh0 = sbh[nl], bh1 = sbh[nl + 1];
#pragma unroll
            for (int rr = 0; rr < 2; rr++) {
                const int m = m0 + wm * 64 + mf * 16 + (lane >> 2) + rr * 8;
                const float k0 = acc[0][mf][nf][rr * 2 + 0] + bz0;
                const float k1 = acc[0][mf][nf][rr * 2 + 1] + bz1;
                const float p0 = acc[1][mf][nf][rr * 2 + 0] + bh0;
                const float p1 = acc[1][mf][nf][rr * 2 + 1] + bh1;
                const float a0 = 1.0f / (1.0f + __expf(k0));
                const float a1 = 1.0f / (1.0f + __expf(k1));
                const float b0 = (1.0f - a0) * g_fn(p0);
                const float b1 = (1.0f - a1) * g_fn(p1);
                *(uint2*)&g_AB[(size_t)m * HDIM + n0 + nl] =
                    make_uint2(pack_ab(a0, b0), pack_ab(a1, b1));
            }
        }
    }
}

// ---------------- single-pass scan: decoupled lookback ----------------
// grid 1024 CTAs x 256 thr; CTA = (batch, hgroup, chunk) via ticket
__global__ void __launch_bounds__(256, 3)
scan_fused_kernel(const float* __restrict__ h0in, float* __restrict__ out)
{
    extern __shared__ __align__(16) uint32_t sdata[];   // 64 KB
    __shared__ int s_ticket;

    const int tid = threadIdx.x;
    if (tid == 0) s_ticket = atomicAdd(&g_Ticket, 1);
    __syncthreads();
    const int ticket = s_ticket;
    const int c     = ticket >> 4;        // chunk: monotone in ticket -> deadlock-free
    const int chain = ticket & 15;
    const int b     = chain >> 2;
    const int g     = chain & 3;

    // --- load 64x256 packed tile into smem ---
    {
        const uint32_t sbase = smem_u32(sdata);
        const uint32_t* src = g_AB + (size_t)(b * SEQ + c * CHUNK) * HDIM + g * 256;
#pragma unroll
        for (int i = 0; i < 16; i++) {
            int v = tid + i * 256;          // 0..4095 16B units
            int row = v >> 6, col16 = v & 63;
            cp_async16(sbase + v * 16, src + (size_t)row * HDIM + col16 * 4);
        }
    }
    CP_COMMIT(); CP_WAIT0();
    __syncthreads();

    // --- local chunk aggregate (A, B) for channel tid ---
    float A = 1.0f, Bc = 0.0f;
#pragma unroll 8
    for (int s = 0; s < CHUNK; s++) {
        float a, bb;
        unpack_ab(sdata[s * 256 + tid], a, bb);
        Bc = fmaf(a, Bc, bb);
        A *= a;
    }

    const int aoffc = (b * NCHUNK + c) * HDIM + g * 256 + tid;    // agg/inc index
    volatile int* flags = g_Flag;
    const int fchain = chain * (NCHUNK * 256) + tid;              // + j*256

    float carry_in;
    if (c == 0) {
        carry_in = g_fn(h0in[b * HDIM + g * 256 + tid]);
    } else {
        // publish aggregate
        g_AggA[aoffc] = A;
        g_AggB[aoffc] = Bc;
        __threadfence();
        flags[fchain + c * 256] = 1;

        // lookback
        float accA = 1.0f, accB = 0.0f;
        for (int j = c - 1;; j--) {
            int f;
            while ((f = flags[fchain + j * 256]) == 0) { __nanosleep(40); }
            __threadfence();
            const int aoffj = (b * NCHUNK + j) * HDIM + g * 256 + tid;
            if (f == 2) {
                carry_in = fmaf(accA, g_Inc[aoffj], accB);
                break;
            }
            const float Aj = g_AggA[aoffj];
            const float Bj = g_AggB[aoffj];
            accB = fmaf(accA, Bj, accB);    // G = G ∘ f_j
            accA *= Aj;
        }
    }

    // publish inclusive
    g_Inc[aoffc] = fmaf(A, carry_in, Bc);
    __threadfence();
    flags[fchain + c * 256] = 2;

    // --- apply + write output ---
    float h = carry_in;
    float* dst = out + (size_t)(b * SEQ + c * CHUNK) * HDIM + g * 256 + tid;
#pragma unroll 8
    for (int s = 0; s < CHUNK; s++) {
        float a, bb;
        unpack_ab(sdata[s * 256 + tid], a, bb);
        h = fmaf(a, h, bb);
        dst[(size_t)s * HDIM] = h;
    }
}

// ---------------- launch ----------------
extern "C" void kernel_launch(void* const* d_in, const int* in_sizes, int n_in,
                              void* d_out, int out_size)
{
    const float* x  = (const float*)d_in[0];
    const float* h0 = (const float*)d_in[1];
    const float* Wz = (const float*)d_in[2];
    const float* bz = (const float*)d_in[3];
    const float* Wh = (const float*)d_in[4];
    const float* bh = (const float*)d_in[5];
    float* out = (float*)d_out;

    cudaFuncSetAttribute(gemm_gate_kernel,
                         cudaFuncAttributeMaxDynamicSharedMemorySize, DYN_SMEM);
    cudaFuncSetAttribute(scan_fused_kernel,
                         cudaFuncAttributeMaxDynamicSharedMemorySize, SCAN_SMEM);

    const int cvt_items = CVT_X + 2 * CVT_W;
    convert_kernel<<<cvt_items / 256, 256>>>(x, Wz, Wh);

    dim3 gGemm(HDIM / BN, M_TOTAL / BM);       // (8, 128)
    gemm_gate_kernel<<<gGemm, 256, DYN_SMEM>>>(bz, bh);

    scan_fused_kernel<<<NCHAIN * NCHUNK, 256, SCAN_SMEM>>>(h0, out);
}